// round 14
// baseline (speedup 1.0000x reference)
#include <cuda_runtime.h>
#include <math.h>
#include <stdint.h>
#include <stddef.h>

// ---------------- problem constants ----------------
#define BATCH   1024
#define EMBED   16
#define S_MAX   16641
#define D_IN    16657
#define H4      1024
#define H2      512
#define H1      256
#define NEXP    7
#define KCHUNK  1024
#define NSPLIT_MAX 17
#define NZ      28
#define XSTRIDE 16672
#define XROWS   (BATCH + 128)

__constant__ int c_sizes[NEXP]  = {9, 25, 81, 289, 1089, 4225, 16641};
__constant__ int c_nsplit[NEXP] = {1, 1, 1, 1, 2, 5, 17};
// heavy-first z order: e6 (17 chunks), e5 (5), e4 (2), e3..e0
__constant__ int c_zo[NZ] = {6,6,6,6,6,6,6,6,6,6,6,6,6,6,6,6,6, 5,5,5,5,5, 4,4, 3,2,1,0};
__constant__ int c_zc[NZ] = {0,1,2,3,4,5,6,7,8,9,10,11,12,13,14,15,16, 0,1,2,3,4, 0,1, 0,0,0,0};

// ---------------- device scratch (static) ----------------
__device__ int   g_cnt[NEXP];
__device__ int   g_off[NEXP + 1];
__device__ int   g_idx[NEXP * BATCH];
__device__ int   g_rowb[BATCH];
__device__ int   g_rowo[BATCH];
__device__ float g_xc[XROWS][XSTRIDE];             // packed X, compact order
__device__ float g_hpart[NSPLIT_MAX][BATCH][H4];   // split-K partials
__device__ float g_h [BATCH * H4];
__device__ float g_z1[BATCH * H2];
__device__ float g_z2[BATCH * H1];

// ---------------- helpers ----------------
__device__ __forceinline__ void mma_tf32(float* c, const uint32_t* a, const uint32_t* b) {
    asm volatile(
        "mma.sync.aligned.m16n8k8.row.col.f32.tf32.tf32.f32 "
        "{%0,%1,%2,%3}, {%4,%5,%6,%7}, {%8,%9}, {%0,%1,%2,%3};"
        : "+f"(c[0]), "+f"(c[1]), "+f"(c[2]), "+f"(c[3])
        : "r"(a[0]), "r"(a[1]), "r"(a[2]), "r"(a[3]), "r"(b[0]), "r"(b[1]));
}
__device__ __forceinline__ void cp16(uint32_t dst, const void* src, bool p) {
    asm volatile("cp.async.cg.shared.global [%0], [%1], 16, %2;"
                 :: "r"(dst), "l"(src), "r"(p ? 16 : 0) : "memory");
}
#define CP_COMMIT() asm volatile("cp.async.commit_group;" ::: "memory")
#define CP_WAIT0()  asm volatile("cp.async.wait_group 0;" ::: "memory")
#define CP_WAIT1()  asm volatile("cp.async.wait_group 1;" ::: "memory")
#define CP_WAIT2()  asm volatile("cp.async.wait_group 2;" ::: "memory")

// ---------------- tile geometry ----------------
#define BK 32
#define BM 64
#define BN 128
#define A_PAD 36
#define B_PAD 132
#define A_TILE (BM * A_PAD)                 // 2304 u32
#define B_TILE (BK * B_PAD)                 // 4224 u32
#define NST 4
#define L1_SMEM (NST * (A_TILE + B_TILE) * 4)    // 104448 B -> 2 CTAs/SM

#define DM 32
#define DN 64
#define DB_PAD 68
#define DA_TILE (DM * A_PAD)                // 1152 u32
#define DB_TILE (BK * DB_PAD)               // 2176 u32
#define D_SMEM (NST * (DA_TILE + DB_TILE) * 4)   // 53248 B

// ---------------------------------------------------------------
__global__ void bucket_kernel(const int* __restrict__ orders)
{
    __shared__ int s_cnt[NEXP];
    __shared__ int s_off[NEXP];
    int b = threadIdx.x;
    if (b < NEXP) s_cnt[b] = 0;
    __syncthreads();
    int o = orders[b];
    int pos = atomicAdd(&s_cnt[o], 1);
    __syncthreads();
    if (b == 0) {
        int a = 0;
        for (int i = 0; i < NEXP; i++) { s_off[i] = a; g_cnt[i] = s_cnt[i]; g_off[i] = a; a += s_cnt[i]; }
        g_off[NEXP] = a;
    }
    __syncthreads();
    g_idx[o * BATCH + pos] = b;
    int row = s_off[o] + pos;
    g_rowb[row] = b;
    g_rowo[row] = o;
}

// ---------------------------------------------------------------
// pack X: compact-row gather of maze slice + embed, zero pad to k-tile
// ---------------------------------------------------------------
__global__ void pack_kernel(const float* __restrict__ mazes,
                            const float* __restrict__ embed)
{
    const int r = blockIdx.x;
    const int b = g_rowb[r];
    const int o = g_rowo[r];
    const int s = c_sizes[o];
    const int Ktot = s + EMBED;
    const int kal  = (Ktot + 31) & ~31;
    const float* src = mazes + (size_t)b * S_MAX;
    float* dst = g_xc[r];
    for (int k = threadIdx.x; k < s; k += 256) dst[k] = src[k];
    for (int k = s + threadIdx.x; k < kal; k += 256)
        dst[k] = (k < Ktot) ? embed[o * EMBED + (k - s)] : 0.f;
}

// ---------------------------------------------------------------
// Layer-1 grouped tf32 GEMM, split-K (KCHUNK=1024), 4-stage cp.async,
// ONE __syncthreads per k-iteration.
// grid = (8 n-tiles, 16 m-tiles, 28 z), 256 threads (8 warps 2x4).
// ---------------------------------------------------------------
__global__ __launch_bounds__(256)
void layer1_mma(const float* __restrict__ W_in,
                const float* __restrict__ b_in)
{
    const int z = blockIdx.z;
    const int o = c_zo[z];
    const int c = c_zc[z];
    const int cnt = g_cnt[o];
    const int m0 = blockIdx.y * BM;
    if (m0 >= cnt) return;
    const int s    = c_sizes[o];
    const int Ktot = s + EMBED;
    const int kbeg = c * KCHUNK;
    if (kbeg >= Ktot) return;
    const int kend = min(kbeg + KCHUNK, Ktot);
    const int n0   = blockIdx.x * BN;
    const int ns   = c_nsplit[o];

    extern __shared__ uint32_t sm[];
    uint32_t* AsBuf = sm;
    uint32_t* BsBuf = sm + NST * A_TILE;
    const uint32_t smb   = (uint32_t)__cvta_generic_to_shared(sm);
    const uint32_t aOffB = smb;
    const uint32_t bOffB = smb + NST * A_TILE * 4;

    const int tid  = threadIdx.x;
    const int wid  = tid >> 5;
    const int lane = tid & 31;
    const int gid  = lane >> 2;
    const int tig  = lane & 3;
    const int warp_m = (wid >> 2) * 32;
    const int warp_n = (wid & 3) * 32;

    const int arow0 = g_off[o] + m0;
    const float* wexp = W_in + (size_t)o * D_IN * H4;

    float acc[2][4][4];
#pragma unroll
    for (int i = 0; i < 2; i++)
#pragma unroll
        for (int j = 0; j < 4; j++)
#pragma unroll
            for (int q = 0; q < 4; q++) acc[i][j][q] = 0.f;

    const int T = (kend - kbeg + BK - 1) / BK;

    auto issue = [&](int t) {
        const int k0  = kbeg + t * BK;
        const int buf = t % NST;
        // A: 64 rows x 32 k -> 512 float4, 2 per thread (unconditional)
#pragma unroll
        for (int j = 0; j < 2; j++) {
            int cch = tid + j * 256;
            int row = cch >> 3;
            int kc  = (cch & 7) * 4;
            uint32_t dst = aOffB + (uint32_t)(buf * A_TILE + row * A_PAD + kc) * 4;
            cp16(dst, &g_xc[arow0 + row][k0 + kc], true);
        }
        // B: 32 k x 128 n -> 1024 float4, 4 per thread
#pragma unroll
        for (int j = 0; j < 4; j++) {
            int cch = tid + j * 256;
            int kk  = cch >> 5;
            int col = (cch & 31) * 4;
            int k   = k0 + kk;
            bool p  = (k < kend);
            int wr  = p ? ((k < s) ? k : (S_MAX + (k - s))) : 0;
            uint32_t dst = bOffB + (uint32_t)(buf * B_TILE + kk * B_PAD + col) * 4;
            cp16(dst, wexp + (size_t)wr * H4 + n0 + col, p);
        }
        CP_COMMIT();
    };

    issue(0);
    if (T > 1) issue(1);
    if (T > 2) issue(2);
    for (int t = 0; t < T; t++) {
        if (t <= T - 3)      { CP_WAIT2(); }
        else if (t == T - 2) { CP_WAIT1(); }
        else                 { CP_WAIT0(); }
        __syncthreads();

        const uint32_t* As = AsBuf + (t % NST) * A_TILE;
        const uint32_t* Bs = BsBuf + (t % NST) * B_TILE;
#pragma unroll
        for (int kf = 0; kf < 4; kf++) {
            uint32_t a[2][4];
#pragma unroll
            for (int mf = 0; mf < 2; mf++) {
                int r = warp_m + mf * 16 + gid;
                a[mf][0] = As[r * A_PAD + kf * 8 + tig];
                a[mf][1] = As[(r + 8) * A_PAD + kf * 8 + tig];
                a[mf][2] = As[r * A_PAD + kf * 8 + tig + 4];
                a[mf][3] = As[(r + 8) * A_PAD + kf * 8 + tig + 4];
            }
            uint32_t b[4][2];
#pragma unroll
            for (int nf = 0; nf < 4; nf++) {
                int col = warp_n + nf * 8 + gid;
                b[nf][0] = Bs[(kf * 8 + tig) * B_PAD + col];
                b[nf][1] = Bs[(kf * 8 + tig + 4) * B_PAD + col];
            }
#pragma unroll
            for (int mf = 0; mf < 2; mf++)
#pragma unroll
                for (int nf = 0; nf < 4; nf++)
                    mma_tf32(acc[mf][nf], a[mf], b[nf]);
        }
        if (t + 3 < T) issue(t + 3);
    }

    // ---- writeback ----
    const int grow0 = g_off[o] + m0;
#pragma unroll
    for (int mf = 0; mf < 2; mf++) {
#pragma unroll
        for (int h = 0; h < 2; h++) {
            int r = warp_m + mf * 16 + gid + h * 8;
            if (m0 + r < cnt) {
                if (ns == 1) {
                    float* dst = g_h + (size_t)(grow0 + r) * H4 + n0 + warp_n;
                    const float* bs = b_in + (size_t)o * H4 + n0 + warp_n;
#pragma unroll
                    for (int nf = 0; nf < 4; nf++) {
                        float x = acc[mf][nf][h * 2]     + __ldg(bs + nf * 8 + tig * 2);
                        float y = acc[mf][nf][h * 2 + 1] + __ldg(bs + nf * 8 + tig * 2 + 1);
                        x = (x > 0.f) ? x : 0.2f * x;
                        y = (y > 0.f) ? y : 0.2f * y;
                        *(float2*)(dst + nf * 8 + tig * 2) = make_float2(x, y);
                    }
                } else {
                    float* dst = &g_hpart[c][grow0 + r][n0 + warp_n];
#pragma unroll
                    for (int nf = 0; nf < 4; nf++)
                        *(float2*)(dst + nf * 8 + tig * 2) =
                            make_float2(acc[mf][nf][h * 2], acc[mf][nf][h * 2 + 1]);
                }
            }
        }
    }
}

// ---------------------------------------------------------------
// Layer-1 epilogue: multi-split experts only, fixed split order.
// ---------------------------------------------------------------
__global__ void l1_epilogue(const float* __restrict__ b_in)
{
    const int r  = blockIdx.x;
    const int o  = g_rowo[r];
    const int ns = c_nsplit[o];
    if (ns == 1) return;
    const int j  = threadIdx.x * 4;
    float4 v = *(const float4*)(b_in + (size_t)o * H4 + j);
    for (int cc = 0; cc < ns; cc++) {
        float4 p = *(const float4*)(&g_hpart[cc][r][j]);
        v.x += p.x; v.y += p.y; v.z += p.z; v.w += p.w;
    }
    v.x = (v.x > 0.f) ? v.x : 0.2f * v.x;
    v.y = (v.y > 0.f) ? v.y : 0.2f * v.y;
    v.z = (v.z > 0.f) ? v.z : 0.2f * v.z;
    v.w = (v.w > 0.f) ? v.w : 0.2f * v.w;
    *(float4*)(g_h + (size_t)r * H4 + j) = v;
}

// ---------------------------------------------------------------
// Dense tf32 GEMM + bias + leaky, 32x64 tiles, 128 thr, 4-stage,
// single sync per iter. sel=0: g_h@W1->g_z1 ; sel=1: g_z1@W2->g_z2
// ---------------------------------------------------------------
__global__ __launch_bounds__(128)
void dense_mma(const float* __restrict__ B, const float* __restrict__ bias,
               int K, int N, int sel)
{
    const float* A = (sel == 0) ? g_h  : g_z1;
    float*       C = (sel == 0) ? g_z1 : g_z2;
    const int m0 = blockIdx.y * DM;
    const int n0 = blockIdx.x * DN;

    extern __shared__ uint32_t sm[];
    uint32_t* sA = sm;
    uint32_t* sB = sm + NST * DA_TILE;
    const uint32_t aOffB = (uint32_t)__cvta_generic_to_shared(sA);
    const uint32_t bOffB = (uint32_t)__cvta_generic_to_shared(sB);

    const int tid  = threadIdx.x;
    const int wid  = tid >> 5;
    const int lane = tid & 31;
    const int gid  = lane >> 2;
    const int tig  = lane & 3;
    const int warp_n = wid * 16;

    float acc[2][2][4];
#pragma unroll
    for (int i = 0; i < 2; i++)
#pragma unroll
        for (int j = 0; j < 2; j++)
#pragma unroll
            for (int q = 0; q < 4; q++) acc[i][j][q] = 0.f;

    auto issue = [&](int t) {
        const int k0  = t * BK;
        const int buf = t % NST;
#pragma unroll
        for (int j = 0; j < 2; j++) {
            int cch = tid + j * 128;
            int row = cch >> 3;
            int kc  = (cch & 7) * 4;
            uint32_t dst = aOffB + (uint32_t)(buf * DA_TILE + row * A_PAD + kc) * 4;
            cp16(dst, A + (size_t)(m0 + row) * K + k0 + kc, true);
        }
#pragma unroll
        for (int j = 0; j < 4; j++) {
            int cch = tid + j * 128;
            int kk  = cch >> 4;
            int col = (cch & 15) * 4;
            uint32_t dst = bOffB + (uint32_t)(buf * DB_TILE + kk * DB_PAD + col) * 4;
            cp16(dst, B + (size_t)(k0 + kk) * N + n0 + col, true);
        }
        CP_COMMIT();
    };

    const int T = K / BK;
    issue(0);
    if (T > 1) issue(1);
    if (T > 2) issue(2);
    for (int t = 0; t < T; t++) {
        if (t <= T - 3)      { CP_WAIT2(); }
        else if (t == T - 2) { CP_WAIT1(); }
        else                 { CP_WAIT0(); }
        __syncthreads();

        const uint32_t* As = sA + (t % NST) * DA_TILE;
        const uint32_t* Bs = sB + (t % NST) * DB_TILE;
#pragma unroll
        for (int kf = 0; kf < 4; kf++) {
            uint32_t a[2][4];
#pragma unroll
            for (int mf = 0; mf < 2; mf++) {
                int r = mf * 16 + gid;
                a[mf][0] = As[r * A_PAD + kf * 8 + tig];
                a[mf][1] = As[(r + 8) * A_PAD + kf * 8 + tig];
                a[mf][2] = As[r * A_PAD + kf * 8 + tig + 4];
                a[mf][3] = As[(r + 8) * A_PAD + kf * 8 + tig + 4];
            }
            uint32_t b[2][2];
#pragma unroll
            for (int nf = 0; nf < 2; nf++) {
                int col = warp_n + nf * 8 + gid;
                b[nf][0] = Bs[(kf * 8 + tig) * DB_PAD + col];
                b[nf][1] = Bs[(kf * 8 + tig + 4) * DB_PAD + col];
            }
#pragma unroll
            for (int mf = 0; mf < 2; mf++)
#pragma unroll
                for (int nf = 0; nf < 2; nf++)
                    mma_tf32(acc[mf][nf], a[mf], b[nf]);
        }
        if (t + 3 < T) issue(t + 3);
    }

#pragma unroll
    for (int mf = 0; mf < 2; mf++) {
#pragma unroll
        for (int h = 0; h < 2; h++) {
            int m = m0 + mf * 16 + gid + h * 8;
            float* dst = C + (size_t)m * N + n0 + warp_n;
            const float* bs = bias + n0 + warp_n;
#pragma unroll
            for (int nf = 0; nf < 2; nf++) {
                float x = acc[mf][nf][h * 2]     + __ldg(bs + nf * 8 + tig * 2);
                float y = acc[mf][nf][h * 2 + 1] + __ldg(bs + nf * 8 + tig * 2 + 1);
                x = (x > 0.f) ? x : 0.2f * x;
                y = (y > 0.f) ? y : 0.2f * y;
                *(float2*)(dst + nf * 8 + tig * 2) = make_float2(x, y);
            }
        }
    }
}

// ---------------------------------------------------------------
// Final 256->1 GEMV + sigmoid, scatter to original batch order.
// ---------------------------------------------------------------
__global__ void l4_kernel(const float* __restrict__ W3,
                          const float* __restrict__ b3,
                          float* __restrict__ out)
{
    const int warp = threadIdx.x >> 5;
    const int lane = threadIdx.x & 31;
    const int r = blockIdx.x * 8 + warp;
    const float* zv = g_z2 + (size_t)r * H1;
    float p = 0.f;
#pragma unroll
    for (int l = 0; l < 8; l++) p += zv[lane + l * 32] * W3[lane + l * 32];
#pragma unroll
    for (int d = 16; d; d >>= 1) p += __shfl_xor_sync(0xffffffffu, p, d);
    if (lane == 0) {
        float x = p + b3[0];
        out[g_rowb[r]] = 1.f / (1.f + expf(-x));
    }
}

// ---------------------------------------------------------------
extern "C" void kernel_launch(void* const* d_in, const int* in_sizes, int n_in,
                              void* d_out, int out_size)
{
    const float* mazes  = (const float*)d_in[0];
    const int*   orders = (const int*)  d_in[1];
    const float* embed  = (const float*)d_in[2];
    const float* W_in   = (const float*)d_in[3];
    const float* b_in   = (const float*)d_in[4];
    const float* W1     = (const float*)d_in[5];
    const float* b1     = (const float*)d_in[6];
    const float* W2     = (const float*)d_in[7];
    const float* b2     = (const float*)d_in[8];
    const float* W3     = (const float*)d_in[9];
    const float* b3     = (const float*)d_in[10];
    float* out = (float*)d_out;

    cudaFuncSetAttribute(layer1_mma, cudaFuncAttributeMaxDynamicSharedMemorySize, L1_SMEM);
    cudaFuncSetAttribute(dense_mma,  cudaFuncAttributeMaxDynamicSharedMemorySize, D_SMEM);

    bucket_kernel<<<1, BATCH>>>(orders);
    pack_kernel<<<BATCH, 256>>>(mazes, embed);
    layer1_mma<<<dim3(H4 / BN, BATCH / BM, NZ), 256, L1_SMEM>>>(W_in, b_in);
    l1_epilogue<<<BATCH, 256>>>(b_in);
    dense_mma<<<dim3(H2 / DN, BATCH / DM), 128, D_SMEM>>>(W1, b1, H4, H2, 0);
    dense_mma<<<dim3(H1 / DN, BATCH / DM), 128, D_SMEM>>>(W2, b2, H2, H1, 1);
    l4_kernel<<<BATCH / 8, 256>>>(W3, b3, out);
}

// round 15
// speedup vs baseline: 1.2468x; 1.2468x over previous
#include <cuda_runtime.h>
#include <cuda_fp16.h>
#include <math.h>
#include <stdint.h>
#include <stddef.h>

// ---------------- problem constants ----------------
#define BATCH   1024
#define EMBED   16
#define S_MAX   16641
#define D_IN    16657
#define H4      1024
#define H2      512
#define H1      256
#define NEXP    7
#define NSPLIT_MAX 17
#define NZ      25
#define XSTRIDE 16672
#define XROWS   (BATCH + 128)

__constant__ int c_sizes[NEXP]  = {9, 25, 81, 289, 1089, 4225, 16641};
__constant__ int c_nsplit[NEXP] = {1, 1, 1, 1, 1, 3, 17};
// heavy-first: e6 (17 x 1024-chunks), e5 (3 x 2048), e4..e0 single
__constant__ int c_zo[NZ] = {6,6,6,6,6,6,6,6,6,6,6,6,6,6,6,6,6, 5,5,5, 4,3,2,1,0};
__constant__ int c_zc[NZ] = {0,1,2,3,4,5,6,7,8,9,10,11,12,13,14,15,16, 0,1,2, 0,0,0,0,0};

// ---------------- device scratch (static) ----------------
__device__ int    g_cnt[NEXP];
__device__ int    g_off[NEXP + 1];
__device__ int    g_idx[NEXP * BATCH];
__device__ int    g_rowb[BATCH];
__device__ int    g_rowo[BATCH];
__device__ __half g_xch[XROWS][XSTRIDE];           // packed X as f16
__device__ float  g_hpart[NSPLIT_MAX][BATCH][H4];  // split-K partials
__device__ float  g_h [BATCH * H4];
__device__ float  g_z1[BATCH * H2];
__device__ float  g_z2[BATCH * H1];

// ---------------- helpers ----------------
__device__ __forceinline__ void mma_tf32(float* c, const uint32_t* a, const uint32_t* b) {
    asm volatile(
        "mma.sync.aligned.m16n8k8.row.col.f32.tf32.tf32.f32 "
        "{%0,%1,%2,%3}, {%4,%5,%6,%7}, {%8,%9}, {%0,%1,%2,%3};"
        : "+f"(c[0]), "+f"(c[1]), "+f"(c[2]), "+f"(c[3])
        : "r"(a[0]), "r"(a[1]), "r"(a[2]), "r"(a[3]), "r"(b[0]), "r"(b[1]));
}
__device__ __forceinline__ void mma_f16(float* c, const uint32_t* a, const uint32_t* b) {
    asm volatile(
        "mma.sync.aligned.m16n8k16.row.col.f32.f16.f16.f32 "
        "{%0,%1,%2,%3}, {%4,%5,%6,%7}, {%8,%9}, {%0,%1,%2,%3};"
        : "+f"(c[0]), "+f"(c[1]), "+f"(c[2]), "+f"(c[3])
        : "r"(a[0]), "r"(a[1]), "r"(a[2]), "r"(a[3]), "r"(b[0]), "r"(b[1]));
}
__device__ __forceinline__ void cp16(uint32_t dst, const void* src, bool p) {
    asm volatile("cp.async.cg.shared.global [%0], [%1], 16, %2;"
                 :: "r"(dst), "l"(src), "r"(p ? 16 : 0) : "memory");
}
#define CP_COMMIT() asm volatile("cp.async.commit_group;" ::: "memory")
#define CP_WAIT0()  asm volatile("cp.async.wait_group 0;" ::: "memory")
#define CP_WAIT1()  asm volatile("cp.async.wait_group 1;" ::: "memory")
#define CP_WAIT2()  asm volatile("cp.async.wait_group 2;" ::: "memory")

__device__ __forceinline__ uint32_t h2u(__half2 h) {
    return *reinterpret_cast<uint32_t*>(&h);
}

// ---------------- tile geometry ----------------
#define BK 32
// layer 1: 64 x 128 tile, 256 threads (8 warps 2x4, warp tile 32x32)
#define BM 64
#define BN 128
#define A_TILEH 1280                 // u32 per A stage (64 rows x 20 u32)
#define B_PADW 136                   // u32 per k-pair row (conflict-free)
#define B_TILEW (16 * B_PADW)        // 2176 u32 per B stage
#define NST1 4                       // A cp.async stages (hazard-free single sync)

// dense (tf32): 32 x 64 tile, 128 threads, 4-stage
#define DM 32
#define DN 64
#define A_PAD 36
#define DB_PAD 68
#define DA_TILE (DM * A_PAD)
#define DB_TILE (BK * DB_PAD)
#define NSTD 4
#define D_SMEM (NSTD * (DA_TILE + DB_TILE) * 4)

// ---------------------------------------------------------------
__global__ void bucket_kernel(const int* __restrict__ orders)
{
    __shared__ int s_cnt[NEXP];
    __shared__ int s_off[NEXP];
    int b = threadIdx.x;
    if (b < NEXP) s_cnt[b] = 0;
    __syncthreads();
    int o = orders[b];
    int pos = atomicAdd(&s_cnt[o], 1);
    __syncthreads();
    if (b == 0) {
        int a = 0;
        for (int i = 0; i < NEXP; i++) { s_off[i] = a; g_cnt[i] = s_cnt[i]; g_off[i] = a; a += s_cnt[i]; }
        g_off[NEXP] = a;
    }
    __syncthreads();
    g_idx[o * BATCH + pos] = b;
    int row = s_off[o] + pos;
    g_rowb[row] = b;
    g_rowo[row] = o;
}

// ---------------------------------------------------------------
// pack X -> f16, compact rows, zero pad to k-tile boundary
// ---------------------------------------------------------------
__global__ void pack_kernel(const float* __restrict__ mazes,
                            const float* __restrict__ embed)
{
    const int r = blockIdx.x;
    const int b = g_rowb[r];
    const int o = g_rowo[r];
    const int s = c_sizes[o];
    const int Ktot = s + EMBED;
    const int kal  = (Ktot + 31) & ~31;
    const float* src = mazes + (size_t)b * S_MAX;
    __half* dst = g_xch[r];
    for (int k = threadIdx.x; k < s; k += 256) dst[k] = __float2half_rn(src[k]);
    for (int k = s + threadIdx.x; k < kal; k += 256)
        dst[k] = __float2half_rn((k < Ktot) ? embed[o * EMBED + (k - s)] : 0.f);
}

// ---------------------------------------------------------------
// Layer-1 grouped fp16 GEMM (fp32 accum), hybrid split-K
// (e6: 1024-chunks, e5: 2048-chunks). A: cp.async f16 4-stage.
// B: LDG f32 -> cvt f16 k-pair smem, register double-buffered.
// ONE __syncthreads per k-iteration.
// grid = (8 n-tiles, 16 m-tiles, 25 z), 256 threads.
// ---------------------------------------------------------------
__global__ __launch_bounds__(256)
void layer1_mma(const float* __restrict__ W_in,
                const float* __restrict__ b_in)
{
    const int z = blockIdx.z;
    const int o = c_zo[z];
    const int c = c_zc[z];
    const int cnt = g_cnt[o];
    const int m0 = blockIdx.y * BM;
    if (m0 >= cnt) return;
    const int s    = c_sizes[o];
    const int Ktot = s + EMBED;
    const int kch  = (o == 6) ? 1024 : 2048;
    const int kbeg = c * kch;
    if (kbeg >= Ktot) return;
    const int kend = min(kbeg + kch, Ktot);
    const int n0   = blockIdx.x * BN;
    const int ns   = c_nsplit[o];

    __shared__ uint32_t sA[NST1 * A_TILEH];   // f16 [m][k], pitch 40 halfs
    __shared__ uint32_t sB[2 * B_TILEW];      // f16 k-pair [k/2][n]
    const uint32_t aOffB = (uint32_t)__cvta_generic_to_shared(sA);

    const int tid  = threadIdx.x;
    const int wid  = tid >> 5;
    const int lane = tid & 31;
    const int gid  = lane >> 2;
    const int tig  = lane & 3;
    const int warp_m = (wid >> 2) * 32;
    const int warp_n = (wid & 3) * 32;

    const int arow0 = g_off[o] + m0;
    const float* wexp = W_in + (size_t)o * D_IN * H4;

    // per-thread B staging coords (2 tasks)
    const int bkp[2]  = { tid >> 5, (tid + 256) >> 5 };
    const int bcol    = (tid & 31) * 4;

    float acc[2][4][4];
#pragma unroll
    for (int i = 0; i < 2; i++)
#pragma unroll
        for (int j = 0; j < 4; j++)
#pragma unroll
            for (int q = 0; q < 4; q++) acc[i][j][q] = 0.f;

    const int T = (kend - kbeg + BK - 1) / BK;

    // A issue: 1 cp16 per thread (64 rows x 32 halfs = 4KB)
    auto issueA = [&](int t) {
        const int k0  = kbeg + t * BK;
        const int buf = t % NST1;
        int row = tid >> 2;
        int kc  = (tid & 3) * 8;               // halfs
        uint32_t dst = aOffB + (uint32_t)buf * A_TILEH * 4 + (uint32_t)(row * 80 + kc * 2);
        cp16(dst, &g_xch[arow0 + row][k0 + kc], true);
        CP_COMMIT();
    };

    float4 bve[2], bvo[2];
    auto ldgB = [&](int t) {
        const int k0 = kbeg + t * BK;
#pragma unroll
        for (int j = 0; j < 2; j++) {
            int ke = k0 + 2 * bkp[j];
            int ko = ke + 1;
            bve[j] = make_float4(0.f, 0.f, 0.f, 0.f);
            bvo[j] = make_float4(0.f, 0.f, 0.f, 0.f);
            if (ke < kend) {
                int wr = (ke < s) ? ke : (S_MAX + (ke - s));
                bve[j] = *(const float4*)(wexp + (size_t)wr * H4 + n0 + bcol);
            }
            if (ko < kend) {
                int wr = (ko < s) ? ko : (S_MAX + (ko - s));
                bvo[j] = *(const float4*)(wexp + (size_t)wr * H4 + n0 + bcol);
            }
        }
    };
    auto stsB = [&](int t) {
        const int buf = t & 1;
#pragma unroll
        for (int j = 0; j < 2; j++) {
            uint4 u;
            u.x = h2u(__floats2half2_rn(bve[j].x, bvo[j].x));
            u.y = h2u(__floats2half2_rn(bve[j].y, bvo[j].y));
            u.z = h2u(__floats2half2_rn(bve[j].z, bvo[j].z));
            u.w = h2u(__floats2half2_rn(bve[j].w, bvo[j].w));
            *(uint4*)&sB[buf * B_TILEW + bkp[j] * B_PADW + bcol] = u;
        }
    };

    // preload
    ldgB(0); stsB(0);
    issueA(0);
    if (T > 1) issueA(1);

    for (int t = 0; t < T; t++) {
        if (t + 1 < T) ldgB(t + 1);
        if (t + 2 < T) { issueA(t + 2); CP_WAIT2(); }
        else if (t + 1 < T) { CP_WAIT1(); }
        else { CP_WAIT0(); }
        __syncthreads();   // covers A-stage visibility AND prev stsB

        const uint32_t* As = sA + (t % NST1) * A_TILEH;
        const uint32_t* Bs = sB + (t & 1) * B_TILEW;
#pragma unroll
        for (int kf = 0; kf < 2; kf++) {           // two k16 chunks
            uint32_t a[2][4];
#pragma unroll
            for (int mf = 0; mf < 2; mf++) {
                int r = warp_m + mf * 16 + gid;
                const int kb = kf * 8 + tig;
                a[mf][0] = As[r * 20 + kb];
                a[mf][1] = As[(r + 8) * 20 + kb];
                a[mf][2] = As[r * 20 + kb + 4];
                a[mf][3] = As[(r + 8) * 20 + kb + 4];
            }
            uint32_t b[4][2];
#pragma unroll
            for (int nf = 0; nf < 4; nf++) {
                int col = warp_n + nf * 8 + gid;
                b[nf][0] = Bs[(kf * 8 + tig) * B_PADW + col];
                b[nf][1] = Bs[(kf * 8 + tig + 4) * B_PADW + col];
            }
#pragma unroll
            for (int mf = 0; mf < 2; mf++)
#pragma unroll
                for (int nf = 0; nf < 4; nf++)
                    mma_f16(acc[mf][nf], a[mf], b[nf]);
        }
        if (t + 1 < T) stsB(t + 1);    // ping-pong buffer; next sync protects
    }

    // ---- writeback ----
    const int grow0 = g_off[o] + m0;
#pragma unroll
    for (int mf = 0; mf < 2; mf++) {
#pragma unroll
        for (int h = 0; h < 2; h++) {
            int r = warp_m + mf * 16 + gid + h * 8;
            if (m0 + r < cnt) {
                if (ns == 1) {
                    float* dst = g_h + (size_t)(grow0 + r) * H4 + n0 + warp_n;
                    const float* bs = b_in + (size_t)o * H4 + n0 + warp_n;
#pragma unroll
                    for (int nf = 0; nf < 4; nf++) {
                        float x = acc[mf][nf][h * 2]     + __ldg(bs + nf * 8 + tig * 2);
                        float y = acc[mf][nf][h * 2 + 1] + __ldg(bs + nf * 8 + tig * 2 + 1);
                        x = (x > 0.f) ? x : 0.2f * x;
                        y = (y > 0.f) ? y : 0.2f * y;
                        *(float2*)(dst + nf * 8 + tig * 2) = make_float2(x, y);
                    }
                } else {
                    float* dst = &g_hpart[c][grow0 + r][n0 + warp_n];
#pragma unroll
                    for (int nf = 0; nf < 4; nf++)
                        *(float2*)(dst + nf * 8 + tig * 2) =
                            make_float2(acc[mf][nf][h * 2], acc[mf][nf][h * 2 + 1]);
                }
            }
        }
    }
}

// ---------------------------------------------------------------
// Layer-1 epilogue: multi-split experts only (5: ns=3, 6: ns=17).
// ---------------------------------------------------------------
__global__ void l1_epilogue(const float* __restrict__ b_in)
{
    const int r  = blockIdx.x;
    const int o  = g_rowo[r];
    const int ns = c_nsplit[o];
    if (ns == 1) return;
    const int j  = threadIdx.x * 4;
    float4 v = *(const float4*)(b_in + (size_t)o * H4 + j);
    if (ns == 3) {
#pragma unroll
        for (int cc = 0; cc < 3; cc++) {
            float4 p = *(const float4*)(&g_hpart[cc][r][j]);
            v.x += p.x; v.y += p.y; v.z += p.z; v.w += p.w;
        }
    } else {
#pragma unroll
        for (int cc = 0; cc < 17; cc++) {
            float4 p = *(const float4*)(&g_hpart[cc][r][j]);
            v.x += p.x; v.y += p.y; v.z += p.z; v.w += p.w;
        }
    }
    v.x = (v.x > 0.f) ? v.x : 0.2f * v.x;
    v.y = (v.y > 0.f) ? v.y : 0.2f * v.y;
    v.z = (v.z > 0.f) ? v.z : 0.2f * v.z;
    v.w = (v.w > 0.f) ? v.w : 0.2f * v.w;
    *(float4*)(g_h + (size_t)r * H4 + j) = v;
}

// ---------------------------------------------------------------
// Dense tf32 GEMM + bias + leaky, 32x64 tiles, 128 thr, 4-stage,
// single sync per iter. sel=0: g_h@W1->g_z1 ; sel=1: g_z1@W2->g_z2
// ---------------------------------------------------------------
__global__ __launch_bounds__(128)
void dense_mma(const float* __restrict__ B, const float* __restrict__ bias,
               int K, int N, int sel)
{
    const float* A = (sel == 0) ? g_h  : g_z1;
    float*       C = (sel == 0) ? g_z1 : g_z2;
    const int m0 = blockIdx.y * DM;
    const int n0 = blockIdx.x * DN;

    extern __shared__ uint32_t sm[];
    uint32_t* sAd = sm;
    uint32_t* sBd = sm + NSTD * DA_TILE;
    const uint32_t aOffB = (uint32_t)__cvta_generic_to_shared(sAd);
    const uint32_t bOffB = (uint32_t)__cvta_generic_to_shared(sBd);

    const int tid  = threadIdx.x;
    const int wid  = tid >> 5;
    const int lane = tid & 31;
    const int gid  = lane >> 2;
    const int tig  = lane & 3;
    const int warp_n = wid * 16;

    float acc[2][2][4];
#pragma unroll
    for (int i = 0; i < 2; i++)
#pragma unroll
        for (int j = 0; j < 2; j++)
#pragma unroll
            for (int q = 0; q < 4; q++) acc[i][j][q] = 0.f;

    auto issue = [&](int t) {
        const int k0  = t * BK;
        const int buf = t % NSTD;
#pragma unroll
        for (int j = 0; j < 2; j++) {
            int cch = tid + j * 128;
            int row = cch >> 3;
            int kc  = (cch & 7) * 4;
            uint32_t dst = aOffB + (uint32_t)(buf * DA_TILE + row * A_PAD + kc) * 4;
            cp16(dst, A + (size_t)(m0 + row) * K + k0 + kc, true);
        }
#pragma unroll
        for (int j = 0; j < 4; j++) {
            int cch = tid + j * 128;
            int kk  = cch >> 4;
            int col = (cch & 15) * 4;
            uint32_t dst = bOffB + (uint32_t)(buf * DB_TILE + kk * DB_PAD + col) * 4;
            cp16(dst, B + (size_t)(k0 + kk) * N + n0 + col, true);
        }
        CP_COMMIT();
    };

    const int T = K / BK;
    issue(0);
    if (T > 1) issue(1);
    if (T > 2) issue(2);
    for (int t = 0; t < T; t++) {
        if (t <= T - 3)      { CP_WAIT2(); }
        else if (t == T - 2) { CP_WAIT1(); }
        else                 { CP_WAIT0(); }
        __syncthreads();

        const uint32_t* As = sAd + (t % NSTD) * DA_TILE;
        const uint32_t* Bs = sBd + (t % NSTD) * DB_TILE;
#pragma unroll
        for (int kf = 0; kf < 4; kf++) {
            uint32_t a[2][4];
#pragma unroll
            for (int mf = 0; mf < 2; mf++) {
                int r = mf * 16 + gid;
                a[mf][0] = As[r * A_PAD + kf * 8 + tig];
                a[mf][1] = As[(r + 8) * A_PAD + kf * 8 + tig];
                a[mf][2] = As[r * A_PAD + kf * 8 + tig + 4];
                a[mf][3] = As[(r + 8) * A_PAD + kf * 8 + tig + 4];
            }
            uint32_t b[2][2];
#pragma unroll
            for (int nf = 0; nf < 2; nf++) {
                int col = warp_n + nf * 8 + gid;
                b[nf][0] = Bs[(kf * 8 + tig) * DB_PAD + col];
                b[nf][1] = Bs[(kf * 8 + tig + 4) * DB_PAD + col];
            }
#pragma unroll
            for (int mf = 0; mf < 2; mf++)
#pragma unroll
                for (int nf = 0; nf < 2; nf++)
                    mma_tf32(acc[mf][nf], a[mf], b[nf]);
        }
        if (t + 3 < T) issue(t + 3);
    }

#pragma unroll
    for (int mf = 0; mf < 2; mf++) {
#pragma unroll
        for (int h = 0; h < 2; h++) {
            int m = m0 + mf * 16 + gid + h * 8;
            float* dst = C + (size_t)m * N + n0 + warp_n;
            const float* bs = bias + n0 + warp_n;
#pragma unroll
            for (int nf = 0; nf < 2; nf++) {
                float x = acc[mf][nf][h * 2]     + __ldg(bs + nf * 8 + tig * 2);
                float y = acc[mf][nf][h * 2 + 1] + __ldg(bs + nf * 8 + tig * 2 + 1);
                x = (x > 0.f) ? x : 0.2f * x;
                y = (y > 0.f) ? y : 0.2f * y;
                *(float2*)(dst + nf * 8 + tig * 2) = make_float2(x, y);
            }
        }
    }
}

// ---------------------------------------------------------------
// Final 256->1 GEMV + sigmoid, scatter to original batch order.
// ---------------------------------------------------------------
__global__ void l4_kernel(const float* __restrict__ W3,
                          const float* __restrict__ b3,
                          float* __restrict__ out)
{
    const int warp = threadIdx.x >> 5;
    const int lane = threadIdx.x & 31;
    const int r = blockIdx.x * 8 + warp;
    const float* zv = g_z2 + (size_t)r * H1;
    float p = 0.f;
#pragma unroll
    for (int l = 0; l < 8; l++) p += zv[lane + l * 32] * W3[lane + l * 32];
#pragma unroll
    for (int d = 16; d; d >>= 1) p += __shfl_xor_sync(0xffffffffu, p, d);
    if (lane == 0) {
        float x = p + b3[0];
        out[g_rowb[r]] = 1.f / (1.f + expf(-x));
    }
}

// ---------------------------------------------------------------
extern "C" void kernel_launch(void* const* d_in, const int* in_sizes, int n_in,
                              void* d_out, int out_size)
{
    const float* mazes  = (const float*)d_in[0];
    const int*   orders = (const int*)  d_in[1];
    const float* embed  = (const float*)d_in[2];
    const float* W_in   = (const float*)d_in[3];
    const float* b_in   = (const float*)d_in[4];
    const float* W1     = (const float*)d_in[5];
    const float* b1     = (const float*)d_in[6];
    const float* W2     = (const float*)d_in[7];
    const float* b2     = (const float*)d_in[8];
    const float* W3     = (const float*)d_in[9];
    const float* b3     = (const float*)d_in[10];
    float* out = (float*)d_out;

    cudaFuncSetAttribute(dense_mma, cudaFuncAttributeMaxDynamicSharedMemorySize, D_SMEM);

    bucket_kernel<<<1, BATCH>>>(orders);
    pack_kernel<<<BATCH, 256>>>(mazes, embed);
    layer1_mma<<<dim3(H4 / BN, BATCH / BM, NZ), 256>>>(W_in, b_in);
    l1_epilogue<<<BATCH, 256>>>(b_in);
    dense_mma<<<dim3(H2 / DN, BATCH / DM), 128, D_SMEM>>>(W1, b1, H4, H2, 0);
    dense_mma<<<dim3(H1 / DN, BATCH / DM), 128, D_SMEM>>>(W2, b2, H2, H1, 1);
    l4_kernel<<<BATCH / 8, 256>>>(W3, b3, out);
}

// round 17
// speedup vs baseline: 1.3070x; 1.0483x over previous
#include <cuda_runtime.h>
#include <cuda_fp16.h>
#include <math.h>
#include <stdint.h>
#include <stddef.h>

// ---------------- problem constants ----------------
#define BATCH   1024
#define EMBED   16
#define S_MAX   16641
#define D_IN    16657
#define H4      1024
#define H2      512
#define H1      256
#define NEXP    7
#define KCH     1024
#define NSPLIT_MAX 17
#define NZ      28
#define XSTRIDE 16672
#define XROWS   (BATCH + 128)

__constant__ int c_sizes[NEXP]  = {9, 25, 81, 289, 1089, 4225, 16641};
__constant__ int c_nsplit[NEXP] = {1, 1, 1, 1, 2, 5, 17};
// heavy-first: e6 x17, e5 x5, e4 x2, e3..e0
__constant__ int c_zo[NZ] = {6,6,6,6,6,6,6,6,6,6,6,6,6,6,6,6,6, 5,5,5,5,5, 4,4, 3,2,1,0};
__constant__ int c_zc[NZ] = {0,1,2,3,4,5,6,7,8,9,10,11,12,13,14,15,16, 0,1,2,3,4, 0,1, 0,0,0,0};

// ---------------- device scratch (static) ----------------
__device__ int    g_cnt[NEXP];
__device__ int    g_off[NEXP + 1];
__device__ int    g_rowb[BATCH];
__device__ int    g_rowo[BATCH];
__device__ __half g_xch[XROWS][XSTRIDE];           // packed X as f16 (zero-init)
__device__ float  g_hpart[NSPLIT_MAX][BATCH][H4];  // split-K partials
__device__ __half g_hh [BATCH * H4];               // layer-1 activations (f16)
__device__ __half g_z1h[BATCH * H2];               // layer-2 activations (f16)
__device__ float  g_z2 [BATCH * H1];
// ---------------- helpers ----------------
__device__ __forceinline__ void mma_f16(float* c, const uint32_t* a, const uint32_t* b) {
    asm volatile(
        "mma.sync.aligned.m16n8k16.row.col.f32.f16.f16.f32 "
        "{%0,%1,%2,%3}, {%4,%5,%6,%7}, {%8,%9}, {%0,%1,%2,%3};"
        : "+f"(c[0]), "+f"(c[1]), "+f"(c[2]), "+f"(c[3])
        : "r"(a[0]), "r"(a[1]), "r"(a[2]), "r"(a[3]), "r"(b[0]), "r"(b[1]));
}
__device__ __forceinline__ void cp16(uint32_t dst, const void* src, bool p) {
    asm volatile("cp.async.cg.shared.global [%0], [%1], 16, %2;"
                 :: "r"(dst), "l"(src), "r"(p ? 16 : 0) : "memory");
}
#define CP_COMMIT() asm volatile("cp.async.commit_group;" ::: "memory")
#define CP_WAIT0()  asm volatile("cp.async.wait_group 0;" ::: "memory")
#define CP_WAIT1()  asm volatile("cp.async.wait_group 1;" ::: "memory")
#define CP_WAIT2()  asm volatile("cp.async.wait_group 2;" ::: "memory")

__device__ __forceinline__ uint32_t h2u(__half2 h) {
    return *reinterpret_cast<uint32_t*>(&h);
}

// ---------------- tile geometry ----------------
#define BK 32
// layer 1: 64 x 128, 256 threads (8 warps 2x4, warp tile 32x32)
#define BM 64
#define BN 128
#define A_TILEH 1280                 // u32 per A stage (64 rows x 20 u32)
#define B_PADW 136                   // u32 per k-pair row (conflict-free)
#define B_TILEW (16 * B_PADW)        // 2176 u32 per B stage
#define NST1 4

// dense fp16: 32 x 64, 128 threads (4 warps 2x2, warp tile 16x32)
#define DA_T  640                    // u32 per A stage (32 rows x 20 u32)
#define DB_PW 72                     // u32 per k-pair row (72 mod 32 = 8 -> conflict-free)
#define DB_T  (16 * DB_PW)           // 1152 u32 per B stage
#define NSTD  4

// ---------------------------------------------------------------
// pack X -> f16 AND atomic-free bucketing (deterministic scan).
// One CTA per batch element b.
// ---------------------------------------------------------------
__global__ void pack_kernel(const float* __restrict__ mazes,
                            const float* __restrict__ embed,
                            const int*   __restrict__ orders)
{
    const int b   = blockIdx.x;
    const int tid = threadIdx.x;
    const int o   = orders[b];

    __shared__ int sh_lt, sh_eq;
    __shared__ int sh_cnt[NEXP];
    if (tid == 0) { sh_lt = 0; sh_eq = 0; }
    if (tid < NEXP) sh_cnt[tid] = 0;
    __syncthreads();

    int lt = 0, eq = 0;
    for (int i = tid; i < BATCH; i += 256) {
        int oi = orders[i];
        lt += (oi < o);
        eq += (oi == o && i < b);
        if (b == 0) atomicAdd(&sh_cnt[oi], 1);
    }
    atomicAdd(&sh_lt, lt);
    atomicAdd(&sh_eq, eq);
    __syncthreads();
    const int r = sh_lt + sh_eq;        // compact row (expert-major, stable)

    if (tid == 0) { g_rowb[r] = b; g_rowo[r] = o; }
    if (b == 0 && tid == 0) {
        int a = 0;
        for (int i = 0; i < NEXP; i++) { g_off[i] = a; g_cnt[i] = sh_cnt[i]; a += sh_cnt[i]; }
        g_off[NEXP] = a;
    }

    const int s    = c_sizes[o];
    const int Ktot = s + EMBED;
    const int kal  = (Ktot + 31) & ~31;
    const float* src = mazes + (size_t)b * S_MAX;
    __half* dst = g_xch[r];
    for (int k = tid; k < s; k += 256) dst[k] = __float2half_rn(src[k]);
    for (int k = s + tid; k < kal; k += 256)
        dst[k] = __float2half_rn((k < Ktot) ? embed[o * EMBED + (k - s)] : 0.f);
}

// ---------------------------------------------------------------
// Layer-1 grouped fp16 GEMM (fp32 accum), uniform 1024 split-K.
// A: cp.async f16 4-stage. B: LDG f32 -> cvt f16 k-pair, 2-stage.
// ONE __syncthreads per k-iteration.
// grid = (8 n-tiles, 16 m-tiles, 28 z), 256 threads.
// ---------------------------------------------------------------
__global__ __launch_bounds__(256)
void layer1_mma(const float* __restrict__ W_in,
                const float* __restrict__ b_in)
{
    const int z = blockIdx.z;
    const int o = c_zo[z];
    const int c = c_zc[z];
    const int cnt = g_cnt[o];
    const int m0 = blockIdx.y * BM;
    if (m0 >= cnt) return;
    const int s    = c_sizes[o];
    const int Ktot = s + EMBED;
    const int kbeg = c * KCH;
    if (kbeg >= Ktot) return;
    const int kend = min(kbeg + KCH, Ktot);
    const int n0   = blockIdx.x * BN;
    const int ns   = c_nsplit[o];

    __shared__ uint32_t sA[NST1 * A_TILEH];
    __shared__ uint32_t sB[2 * B_TILEW];
    const uint32_t aOffB = (uint32_t)__cvta_generic_to_shared(sA);

    const int tid  = threadIdx.x;
    const int wid  = tid >> 5;
    const int lane = tid & 31;
    const int gid  = lane >> 2;
    const int tig  = lane & 3;
    const int warp_m = (wid >> 2) * 32;
    const int warp_n = (wid & 3) * 32;

    const int arow0 = g_off[o] + m0;
    const float* wexp = W_in + (size_t)o * D_IN * H4;

    const int bkp[2] = { tid >> 5, (tid + 256) >> 5 };
    const int bcol   = (tid & 31) * 4;

    float acc[2][4][4];
#pragma unroll
    for (int i = 0; i < 2; i++)
#pragma unroll
        for (int j = 0; j < 4; j++)
#pragma unroll
            for (int q = 0; q < 4; q++) acc[i][j][q] = 0.f;

    const int T = (kend - kbeg + BK - 1) / BK;

    auto issueA = [&](int t) {
        const int k0  = kbeg + t * BK;
        const int buf = t % NST1;
        int row = tid >> 2;
        int kc  = (tid & 3) * 8;
        uint32_t dst = aOffB + (uint32_t)buf * A_TILEH * 4 + (uint32_t)(row * 80 + kc * 2);
        cp16(dst, &g_xch[arow0 + row][k0 + kc], true);
        CP_COMMIT();
    };

    float4 bve[2], bvo[2];
    auto ldgB = [&](int t) {
        const int k0 = kbeg + t * BK;
#pragma unroll
        for (int j = 0; j < 2; j++) {
            int ke = k0 + 2 * bkp[j];
            int ko = ke + 1;
            bve[j] = make_float4(0.f, 0.f, 0.f, 0.f);
            bvo[j] = make_float4(0.f, 0.f, 0.f, 0.f);
            if (ke < kend) {
                int wr = (ke < s) ? ke : (S_MAX + (ke - s));
                bve[j] = *(const float4*)(wexp + (size_t)wr * H4 + n0 + bcol);
            }
            if (ko < kend) {
                int wr = (ko < s) ? ko : (S_MAX + (ko - s));
                bvo[j] = *(const float4*)(wexp + (size_t)wr * H4 + n0 + bcol);
            }
        }
    };
    auto stsB = [&](int t) {
        const int buf = t & 1;
#pragma unroll
        for (int j = 0; j < 2; j++) {
            uint4 u;
            u.x = h2u(__floats2half2_rn(bve[j].x, bvo[j].x));
            u.y = h2u(__floats2half2_rn(bve[j].y, bvo[j].y));
            u.z = h2u(__floats2half2_rn(bve[j].z, bvo[j].z));
            u.w = h2u(__floats2half2_rn(bve[j].w, bvo[j].w));
            *(uint4*)&sB[buf * B_TILEW + bkp[j] * B_PADW + bcol] = u;
        }
    };

    ldgB(0); stsB(0);
    issueA(0);
    if (T > 1) issueA(1);

    for (int t = 0; t < T; t++) {
        if (t + 1 < T) ldgB(t + 1);
        if (t + 2 < T) { issueA(t + 2); CP_WAIT2(); }
        else if (t + 1 < T) { CP_WAIT1(); }
        else { CP_WAIT0(); }
        __syncthreads();

        const uint32_t* As = sA + (t % NST1) * A_TILEH;
        const uint32_t* Bs = sB + (t & 1) * B_TILEW;
#pragma unroll
        for (int kf = 0; kf < 2; kf++) {
            uint32_t a[2][4];
#pragma unroll
            for (int mf = 0; mf < 2; mf++) {
                int r = warp_m + mf * 16 + gid;
                const int kb = kf * 8 + tig;
                a[mf][0] = As[r * 20 + kb];
                a[mf][1] = As[(r + 8) * 20 + kb];
                a[mf][2] = As[r * 20 + kb + 4];
                a[mf][3] = As[(r + 8) * 20 + kb + 4];
            }
            uint32_t b[4][2];
#pragma unroll
            for (int nf = 0; nf < 4; nf++) {
                int col = warp_n + nf * 8 + gid;
                b[nf][0] = Bs[(kf * 8 + tig) * B_PADW + col];
                b[nf][1] = Bs[(kf * 8 + tig + 4) * B_PADW + col];
            }
#pragma unroll
            for (int mf = 0; mf < 2; mf++)
#pragma unroll
                for (int nf = 0; nf < 4; nf++)
                    mma_f16(acc[mf][nf], a[mf], b[nf]);
        }
        if (t + 1 < T) stsB(t + 1);
    }

    // ---- writeback ----
    const int grow0 = g_off[o] + m0;
#pragma unroll
    for (int mf = 0; mf < 2; mf++) {
#pragma unroll
        for (int h = 0; h < 2; h++) {
            int r = warp_m + mf * 16 + gid + h * 8;
            if (m0 + r < cnt) {
                if (ns == 1) {
                    __half* dst = g_hh + (size_t)(grow0 + r) * H4 + n0 + warp_n;
                    const float* bs = b_in + (size_t)o * H4 + n0 + warp_n;
#pragma unroll
                    for (int nf = 0; nf < 4; nf++) {
                        float x = acc[mf][nf][h * 2]     + __ldg(bs + nf * 8 + tig * 2);
                        float y = acc[mf][nf][h * 2 + 1] + __ldg(bs + nf * 8 + tig * 2 + 1);
                        x = (x > 0.f) ? x : 0.2f * x;
                        y = (y > 0.f) ? y : 0.2f * y;
                        *(uint32_t*)(dst + nf * 8 + tig * 2) = h2u(__floats2half2_rn(x, y));
                    }
                } else {
                    float* dst = &g_hpart[c][grow0 + r][n0 + warp_n];
#pragma unroll
                    for (int nf = 0; nf < 4; nf++)
                        *(float2*)(dst + nf * 8 + tig * 2) =
                            make_float2(acc[mf][nf][h * 2], acc[mf][nf][h * 2 + 1]);
                }
            }
        }
    }
}

// ---------------------------------------------------------------
// Layer-1 epilogue: multi-split experts only (ns in {2,5,17}).
// ---------------------------------------------------------------
__global__ void l1_epilogue(const float* __restrict__ b_in)
{
    const int r  = blockIdx.x;
    const int o  = g_rowo[r];
    const int ns = c_nsplit[o];
    if (ns == 1) return;
    const int j  = threadIdx.x * 4;
    float4 v = *(const float4*)(b_in + (size_t)o * H4 + j);
    for (int cc = 0; cc < ns; cc++) {
        float4 p = *(const float4*)(&g_hpart[cc][r][j]);
        v.x += p.x; v.y += p.y; v.z += p.z; v.w += p.w;
    }
    v.x = (v.x > 0.f) ? v.x : 0.2f * v.x;
    v.y = (v.y > 0.f) ? v.y : 0.2f * v.y;
    v.z = (v.z > 0.f) ? v.z : 0.2f * v.z;
    v.w = (v.w > 0.f) ? v.w : 0.2f * v.w;
    uint2 out;
    out.x = h2u(__floats2half2_rn(v.x, v.y));
    out.y = h2u(__floats2half2_rn(v.z, v.w));
    *(uint2*)(g_hh + (size_t)r * H4 + j) = out;
}

// ---------------------------------------------------------------
// Dense fp16 GEMM + bias + leaky. 32x64 tiles, 128 thr (4 warps 2x2,
// warp tile 16x32). A: f16 cp.async 4-stage. B: LDG f32 -> cvt f16
// k-pair 2-stage. Single sync per iter.
// sel=0: g_hh @ W1 -> g_z1h ; sel=1: g_z1h @ W2 -> g_z2 (f32)
// ---------------------------------------------------------------
__global__ __launch_bounds__(128)
void dense_fp16(const float* __restrict__ B, const float* __restrict__ bias,
                int K, int N, int sel)
{
    const __half* A = (sel == 0) ? g_hh : g_z1h;
    const int m0 = blockIdx.y * 32;
    const int n0 = blockIdx.x * 64;

    __shared__ uint32_t sA[NSTD * DA_T];
    __shared__ uint32_t sB[2 * DB_T];
    const uint32_t aOffB = (uint32_t)__cvta_generic_to_shared(sA);

    const int tid  = threadIdx.x;
    const int wid  = tid >> 5;
    const int lane = tid & 31;
    const int gid  = lane >> 2;
    const int tig  = lane & 3;
    const int warp_m = (wid >> 1) * 16;
    const int warp_n = (wid & 1) * 32;

    const int bkp[2] = { tid >> 4, 8 + (tid >> 4) };
    const int bcol   = (tid & 15) * 4;

    float acc[4][4];
#pragma unroll
    for (int j = 0; j < 4; j++)
#pragma unroll
        for (int q = 0; q < 4; q++) acc[j][q] = 0.f;

    const int T = K / BK;

    auto issueA = [&](int t) {
        const int k0  = t * BK;
        const int buf = t % NSTD;
        int row = tid >> 2;
        int kc  = (tid & 3) * 8;
        uint32_t dst = aOffB + (uint32_t)buf * DA_T * 4 + (uint32_t)(row * 80 + kc * 2);
        cp16(dst, A + (size_t)(m0 + row) * K + k0 + kc, true);
        CP_COMMIT();
    };

    float4 bve[2], bvo[2];
    auto ldgB = [&](int t) {
        const int k0 = t * BK;
#pragma unroll
        for (int j = 0; j < 2; j++) {
            int ke = k0 + 2 * bkp[j];
            bve[j] = *(const float4*)(B + (size_t)ke * N + n0 + bcol);
            bvo[j] = *(const float4*)(B + (size_t)(ke + 1) * N + n0 + bcol);
        }
    };
    auto stsB = [&](int t) {
        const int buf = t & 1;
#pragma unroll
        for (int j = 0; j < 2; j++) {
            uint4 u;
            u.x = h2u(__floats2half2_rn(bve[j].x, bvo[j].x));
            u.y = h2u(__floats2half2_rn(bve[j].y, bvo[j].y));
            u.z = h2u(__floats2half2_rn(bve[j].z, bvo[j].z));
            u.w = h2u(__floats2half2_rn(bve[j].w, bvo[j].w));
            *(uint4*)&sB[buf * DB_T + bkp[j] * DB_PW + bcol] = u;
        }
    };

    ldgB(0); stsB(0);
    issueA(0);
    if (T > 1) issueA(1);

    for (int t = 0; t < T; t++) {
        if (t + 1 < T) ldgB(t + 1);
        if (t + 2 < T) { issueA(t + 2); CP_WAIT2(); }
        else if (t + 1 < T) { CP_WAIT1(); }
        else { CP_WAIT0(); }
        __syncthreads();

        const uint32_t* As = sA + (t % NSTD) * DA_T;
        const uint32_t* Bs = sB + (t & 1) * DB_T;
#pragma unroll
        for (int kf = 0; kf < 2; kf++) {
            uint32_t a[4];
            {
                int r = warp_m + gid;
                const int kb = kf * 8 + tig;
                a[0] = As[r * 20 + kb];
                a[1] = As[(r + 8) * 20 + kb];
                a[2] = As[r * 20 + kb + 4];
                a[3] = As[(r + 8) * 20 + kb + 4];
            }
            uint32_t b[4][2];
#pragma unroll
            for (int nf = 0; nf < 4; nf++) {
                int col = warp_n + nf * 8 + gid;
                b[nf][0] = Bs[(kf * 8 + tig) * DB_PW + col];
                b[nf][1] = Bs[(kf * 8 + tig + 4) * DB_PW + col];
            }
#pragma unroll
            for (int nf = 0; nf < 4; nf++)
                mma_f16(acc[nf], a, b[nf]);
        }
        if (t + 1 < T) stsB(t + 1);
    }

    // ---- epilogue: bias + leaky ----
#pragma unroll
    for (int h = 0; h < 2; h++) {
        int m = m0 + warp_m + gid + h * 8;
        const float* bs = bias + n0 + warp_n;
#pragma unroll
        for (int nf = 0; nf < 4; nf++) {
            float x = acc[nf][h * 2]     + __ldg(bs + nf * 8 + tig * 2);
            float y = acc[nf][h * 2 + 1] + __ldg(bs + nf * 8 + tig * 2 + 1);
            x = (x > 0.f) ? x : 0.2f * x;
            y = (y > 0.f) ? y : 0.2f * y;
            if (sel == 0) {
                *(uint32_t*)(g_z1h + (size_t)m * N + n0 + warp_n + nf * 8 + tig * 2) =
                    h2u(__floats2half2_rn(x, y));
            } else {
                *(float2*)(g_z2 + (size_t)m * N + n0 + warp_n + nf * 8 + tig * 2) =
                    make_float2(x, y);
            }
        }
    }
}

// ---------------------------------------------------------------
// Final 256->1 GEMV + sigmoid, scatter to original batch order.
// ---------------------------------------------------------------
__global__ void l4_kernel(const float* __restrict__ W3,
                          const float* __restrict__ b3,
                          float* __restrict__ out)
{
    const int warp = threadIdx.x >> 5;
    const int lane = threadIdx.x & 31;
    const int r = blockIdx.x * 8 + warp;
    const float* zv = g_z2 + (size_t)r * H1;
    float p = 0.f;
#pragma unroll
    for (int l = 0; l < 8; l++) p += zv[lane + l * 32] * W3[lane + l * 32];
#pragma unroll
    for (int d = 16; d; d >>= 1) p += __shfl_xor_sync(0xffffffffu, p, d);
    if (lane == 0) {
        float x = p + b3[0];
        out[g_rowb[r]] = 1.f / (1.f + expf(-x));
    }
}

// ---------------------------------------------------------------
extern "C" void kernel_launch(void* const* d_in, const int* in_sizes, int n_in,
                              void* d_out, int out_size)
{
    const float* mazes  = (const float*)d_in[0];
    const int*   orders = (const int*)  d_in[1];
    const float* embed  = (const float*)d_in[2];
    const float* W_in   = (const float*)d_in[3];
    const float* b_in   = (const float*)d_in[4];
    const float* W1     = (const float*)d_in[5];
    const float* b1     = (const float*)d_in[6];
    const float* W2     = (const float*)d_in[7];
    const float* b2     = (const float*)d_in[8];
    const float* W3     = (const float*)d_in[9];
    const float* b3     = (const float*)d_in[10];
    float* out = (float*)d_out;

    pack_kernel<<<BATCH, 256>>>(mazes, embed, orders);
    layer1_mma<<<dim3(H4 / BN, BATCH / BM, NZ), 256>>>(W_in, b_in);
    l1_epilogue<<<BATCH, 256>>>(b_in);
    dense_fp16<<<dim3(H2 / 64, BATCH / 32), 128>>>(W1, b1, H4, H2, 0);
    dense_fp16<<<dim3(H1 / 64, BATCH / 32), 128>>>(W2, b2, H2, H1, 1);
    l4_kernel<<<BATCH / 8, 256>>>(W3, b3, out);
}